// round 13
// baseline (speedup 1.0000x reference)
#include <cuda_runtime.h>
#include <cuda_fp16.h>
#include <cstdint>

typedef unsigned int u32;

#define E_TOT   200000
#define GRID    148
#define NTHR    256
#define NWARP   8
#define UNITS   6260            // 20 r-values x 313 node-blocks of 32

#define OFF_W0  0
#define OFF_W1  4096
#define OFF_T   36864
#define OFF_TB  102400
#define OFF_B0  103424
#define OFF_B1  103936
#define SMEM_BYTES 104448

__device__ uint4 gWimg[SMEM_BYTES / 16];
__device__ u32 gUC;             // work-stealing unit counter

// XOR-swizzled byte offset within a 256B-row fp16 image: row n, col k (0..127)
__host__ __device__ __forceinline__ u32 sw_off(int n, int k) {
    int chunk = k >> 3;
    return (u32)(n * 256 + (((chunk ^ (n & 7)) << 4) | ((k & 7) << 1)));
}

__device__ __forceinline__ void put16(u32 off, u32 boff, float v) {
    *(__half*)((char*)gWimg + off + boff) = __float2half(v);
}

// blocks 0..71: W0/W1 images + biases. blocks 72..103: T' rows (m*32+o) + Tb.
// block 0 thread 0 also resets the work-stealing counter (runs before msg_kernel
// in stream order, so every graph replay starts from 0).
__global__ void prep(const float* __restrict__ W0, const float* __restrict__ W1,
                     const float* __restrict__ b0, const float* __restrict__ b1,
                     const float* __restrict__ W2, const float* __restrict__ b2)
{
    int blk = blockIdx.x, tid = threadIdx.x;
    if (blk == 0 && tid == 0) gUC = 0;
    if (blk < 72) {
        int id = blk * 256 + tid;
        if (id < 2048) {                   // W0 [128n][16k], 32B rows, no swizzle
            int n = id >> 4, k = id & 15;
            put16(OFF_W0, (u32)(n * 32 + k * 2), W0[id]);
        } else if (id < 2048 + 16384) {    // W1 [128n][128k], swizzled
            int j = id - 2048;
            put16(OFF_W1, sw_off(j >> 7, j & 127), W1[j]);
        }
        if (id < 128) {
            *(float*)((char*)gWimg + OFF_B0 + id * 4) = b0[id];
            *(float*)((char*)gWimg + OFF_B1 + id * 4) = b1[id];
        }
    } else {
        int o = blk - 72, j = tid & 127;
        if (tid < 128) {
            float s = 0.f;
            #pragma unroll
            for (int i = 0; i < 32; ++i) {
                s += W2[(o * 32 + i) * 128 + j];
                if ((i & 3) == 3) put16(OFF_T, sw_off((i >> 2) * 32 + o, j), s);
            }
        } else if (tid == 128) {
            float sb = 0.f;
            #pragma unroll
            for (int i = 0; i < 32; ++i) {
                sb += b2[o * 32 + i];
                if ((i & 3) == 3)
                    *(float*)((char*)gWimg + OFF_TB + ((i >> 2) * 32 + o) * 4) = sb;
            }
        }
    }
}

// ---------------------------------------------------------------------------
__device__ __forceinline__ u32 smem_u32(const void* p) {
    u32 a;
    asm("{ .reg .u64 t; cvta.to.shared.u64 t, %1; cvt.u32.u64 %0, t; }" : "=r"(a) : "l"(p));
    return a;
}
__device__ __forceinline__ void ldsm4(u32* r, u32 a) {
    asm volatile("ldmatrix.sync.aligned.m8n8.x4.shared.b16 {%0,%1,%2,%3}, [%4];"
        : "=r"(r[0]), "=r"(r[1]), "=r"(r[2]), "=r"(r[3]) : "r"(a));
}
__device__ __forceinline__ void mma(float* d, const u32* a, const u32* b) {
    asm volatile("mma.sync.aligned.m16n8k16.row.col.f32.f16.f16.f32 "
        "{%0,%1,%2,%3}, {%4,%5,%6,%7}, {%8,%9}, {%0,%1,%2,%3};"
        : "+f"(d[0]), "+f"(d[1]), "+f"(d[2]), "+f"(d[3])
        : "r"(a[0]), "r"(a[1]), "r"(a[2]), "r"(a[3]), "r"(b[0]), "r"(b[1]));
}
// 2 mma on one ldsm.x4 for one A-tile
__device__ __forceinline__ void mma2(float* acc, const u32* a, const u32* b) {
    mma(acc,     a, b);
    mma(acc + 4, a, b + 2);
}
__device__ __forceinline__ u32 pack2(float f0, float f1) {
    u32 h;
    asm("cvt.rn.f16x2.f32 %0, %1, %2;" : "=r"(h) : "f"(f1), "f"(f0));
    return h;
}
__device__ __forceinline__ float relu(float x) { return fmaxf(x, 0.f); }

__global__ void __launch_bounds__(NTHR, 1)
msg_kernel(const float* __restrict__ h_w, const float* __restrict__ e_vw,
           float* __restrict__ out)
{
    extern __shared__ unsigned char sraw[];
    const int t = threadIdx.x, lane = t & 31;
    const int lr = lane & 7, g = lane >> 3, q = lane & 3;
    const int kc = 2 * q;
    const int el = lane >> 2;

    // stage weight image (102KB)
    {
        uint4* dst = (uint4*)sraw;
        for (int i = t; i < SMEM_BYTES / 16; i += NTHR) dst[i] = gWimg[i];
    }
    __syncthreads();

    const u32 sb = smem_u32(sraw);
    const float* b0s = (const float*)(sraw + OFF_B0);
    const float* b1s = (const float*)(sraw + OFF_B1);
    const float* Tbs = (const float*)(sraw + OFF_TB);

    // per-slice address bases (unit-invariant)
    u32 rb1[8], sx1[8], ad0[8];
    #pragma unroll
    for (int s = 0; s < 8; ++s) {
        int n = (2 * s + (g >> 1)) * 8 + lr;
        rb1[s] = sb + OFF_W1 + n * 256;
        sx1[s] = (u32)(n & 7) << 4;
        ad0[s] = sb + OFF_W0 + n * 32 + (g & 1) * 16;
    }
    const u32 kxor = (u32)(g & 1) << 4;

    // ---- work stealing: grab first unit ----
    u32 ucur;
    if (lane == 0) ucur = atomicAdd(&gUC, 1u);
    ucur = __shfl_sync(0xffffffffu, ucur, 0);

    while (ucur < UNITS) {
        const int u = (int)ucur;

        // steal next unit early (latency hidden behind this unit's GEMMs)
        u32 unext;
        if (lane == 0) unext = atomicAdd(&gUC, 1u);
        unext = __shfl_sync(0xffffffffu, unext, 0);

        const int r = u % 20, bblk = u / 20;
        const bool vB = bblk < 312;
        const int nA = bblk * 32 + el;
        const int nB = vB ? nA + 16 : nA;
        const size_t geA0 = (size_t)nA * 20 + r, geA1 = geA0 + 160;
        const size_t geB0 = (size_t)nB * 20 + r, geB1 = geB0 + 160;

        // ---- warp-uniform telescoping structure ----
        const int rm = (r * 32) % 20;
        const int i1 = rm ? 20 - rm : 20;
        const int v0 = (r * 32) / 20;
        const int mA = (i1 >> 2) - 1;
        const bool hasB = (i1 + 20) < 32;
        const int mB = hasB ? ((i1 + 20) >> 2) - 1 : 7;

        // ---- per-edge coefficients (2 edges per tile, 2 tiles) ----
        float cA0[2], cA1[2], cB0[2], cB1[2], c70[2], c71[2];
        #pragma unroll
        for (int tl = 0; tl < 2; ++tl) {
            int n0 = (tl ? nB : nA) * 32 + v0;
            float h0a = h_w[n0], h1a = h_w[n0 + 1];
            float h0b = h_w[n0 + 256], h1b = h_w[n0 + 257];
            cA0[tl] = h0a - h1a; cA1[tl] = h0b - h1b;
            if (hasB) {
                float h2a = h_w[n0 + 2], h2b = h_w[n0 + 258];
                cB0[tl] = h1a - h2a; cB1[tl] = h1b - h2b;
                c70[tl] = h2a; c71[tl] = h2b;
            } else {
                cB0[tl] = 0.f; cB1[tl] = 0.f;
                c70[tl] = h1a; c71[tl] = h1b;
            }
        }

        // ---- e fragments, both tiles ----
        u32 ahA[4], ahB[4];
        {
            float2 u0 = *(const float2*)(e_vw + geA0 * 16 + kc);
            float2 u1 = *(const float2*)(e_vw + geA0 * 16 + kc + 8);
            float2 u2 = *(const float2*)(e_vw + geA1 * 16 + kc);
            float2 u3 = *(const float2*)(e_vw + geA1 * 16 + kc + 8);
            ahA[0] = pack2(u0.x, u0.y);
            ahA[1] = pack2(u2.x, u2.y);
            ahA[2] = pack2(u1.x, u1.y);
            ahA[3] = pack2(u3.x, u3.y);
            u0 = *(const float2*)(e_vw + geB0 * 16 + kc);
            u1 = *(const float2*)(e_vw + geB0 * 16 + kc + 8);
            u2 = *(const float2*)(e_vw + geB1 * 16 + kc);
            u3 = *(const float2*)(e_vw + geB1 * 16 + kc + 8);
            ahB[0] = pack2(u0.x, u0.y);
            ahB[1] = pack2(u2.x, u2.y);
            ahB[2] = pack2(u1.x, u1.y);
            ahB[3] = pack2(u3.x, u3.y);
        }

        // ---- fused GEMM0->GEMM1, two N-halves; x1 slices recomputed ----
        u32 x2hA[8][4], x2hB[8][4];
        #pragma unroll
        for (int half = 0; half < 2; ++half) {
            float accA[32], accB[32];
            #pragma unroll
            for (int n2 = 0; n2 < 4; ++n2) {          // init with b1
                int n0 = 16 * (4 * half + n2) + kc;
                float bb00 = b1s[n0], bb01 = b1s[n0 + 1];
                float bb10 = b1s[n0 + 8], bb11 = b1s[n0 + 9];
                float* A = accA + 8 * n2; float* B = accB + 8 * n2;
                A[0]=bb00; A[1]=bb01; A[2]=bb00; A[3]=bb01;
                A[4]=bb10; A[5]=bb11; A[6]=bb10; A[7]=bb11;
                B[0]=bb00; B[1]=bb01; B[2]=bb00; B[3]=bb01;
                B[4]=bb10; B[5]=bb11; B[6]=bb10; B[7]=bb11;
            }
            u32 cw[2][4];
            ldsm4(cw[0], ad0[0]);                     // W0 slice 0, step 0
            #pragma unroll
            for (int s = 0; s < 8; ++s) {
                const u32 kx = ((u32)s << 5) ^ kxor;
                const int b0i = (5 * s) & 1;          // buffer holding W0(s)
                // prefetch W1(s, first ntp of half)
                ldsm4(cw[b0i ^ 1], rb1[4 * half] + (kx ^ sx1[4 * half]));
                // GEMM0 slice s (bias-init, recompute per half)
                float a0A[8], a0B[8];
                {
                    int n0 = 16 * s + kc;
                    float bb00 = b0s[n0], bb01 = b0s[n0 + 1];
                    float bb10 = b0s[n0 + 8], bb11 = b0s[n0 + 9];
                    a0A[0]=bb00; a0A[1]=bb01; a0A[2]=bb00; a0A[3]=bb01;
                    a0A[4]=bb10; a0A[5]=bb11; a0A[6]=bb10; a0A[7]=bb11;
                    a0B[0]=bb00; a0B[1]=bb01; a0B[2]=bb00; a0B[3]=bb01;
                    a0B[4]=bb10; a0B[5]=bb11; a0B[6]=bb10; a0B[7]=bb11;
                }
                mma2(a0A, ahA, cw[b0i]);
                mma2(a0B, ahB, cw[b0i]);
                u32 x1A[4], x1B[4];
                x1A[0] = pack2(relu(a0A[0]), relu(a0A[1]));
                x1A[1] = pack2(relu(a0A[2]), relu(a0A[3]));
                x1A[2] = pack2(relu(a0A[4]), relu(a0A[5]));
                x1A[3] = pack2(relu(a0A[6]), relu(a0A[7]));
                x1B[0] = pack2(relu(a0B[0]), relu(a0B[1]));
                x1B[1] = pack2(relu(a0B[2]), relu(a0B[3]));
                x1B[2] = pack2(relu(a0B[4]), relu(a0B[5]));
                x1B[3] = pack2(relu(a0B[6]), relu(a0B[7]));
                // GEMM1 partial: k-slice s across the N-half
                #pragma unroll
                for (int n2 = 0; n2 < 4; ++n2) {
                    const int bi = (5 * s + 1 + n2) & 1;
                    if (n2 < 3)
                        ldsm4(cw[bi ^ 1], rb1[4 * half + n2 + 1] + (kx ^ sx1[4 * half + n2 + 1]));
                    else if (s < 7)
                        ldsm4(cw[bi ^ 1], ad0[s + 1]);
                    mma2(accA + 8 * n2, x1A, cw[bi]);
                    mma2(accB + 8 * n2, x1B, cw[bi]);
                }
            }
            // relu + pack -> x2 fragments for this half
            #pragma unroll
            for (int n2 = 0; n2 < 4; ++n2) {
                int s2 = 4 * half + n2;
                const float* A = accA + 8 * n2;
                const float* B = accB + 8 * n2;
                x2hA[s2][0] = pack2(relu(A[0]), relu(A[1]));
                x2hA[s2][1] = pack2(relu(A[2]), relu(A[3]));
                x2hA[s2][2] = pack2(relu(A[4]), relu(A[5]));
                x2hA[s2][3] = pack2(relu(A[6]), relu(A[7]));
                x2hB[s2][0] = pack2(relu(B[0]), relu(B[1]));
                x2hB[s2][1] = pack2(relu(B[2]), relu(B[3]));
                x2hB[s2][2] = pack2(relu(B[4]), relu(B[5]));
                x2hB[s2][3] = pack2(relu(B[6]), relu(B[7]));
            }
        }

        // ---- GEMM_D over only the needed m-groups; B shared by both tiles ----
        int   mlist[3] = { mA, 7, mB };
        const int ng = hasB ? 3 : 2;

        float voutA[16], voutB[16];
        #pragma unroll
        for (int i = 0; i < 16; ++i) { voutA[i] = 0.f; voutB[i] = 0.f; }

        for (int grp = 0; grp < ng; ++grp) {
            const int m = mlist[grp];
            float accdA[16], accdB[16];
            #pragma unroll
            for (int ntp = 0; ntp < 2; ++ntp)        // init with Tb
                #pragma unroll
                for (int tile = 0; tile < 2; ++tile) {
                    int o = 16 * ntp + 8 * tile + kc;
                    float tb0 = Tbs[m * 32 + o], tb1 = Tbs[m * 32 + o + 1];
                    float* A = accdA + 8 * ntp + 4 * tile;
                    float* B = accdB + 8 * ntp + 4 * tile;
                    A[0]=tb0; A[1]=tb1; A[2]=tb0; A[3]=tb1;
                    B[0]=tb0; B[1]=tb1; B[2]=tb0; B[3]=tb1;
                }
            u32 rbd[2], sxd[2];
            #pragma unroll
            for (int ntp = 0; ntp < 2; ++ntp) {
                int n = m * 32 + (2 * ntp + (g >> 1)) * 8 + lr;
                rbd[ntp] = sb + OFF_T + n * 256;
                sxd[ntp] = (u32)(n & 7) << 4;
            }
            {
                u32 cw[2][4];
                ldsm4(cw[0], rbd[0] + (kxor ^ sxd[0]));
                #pragma unroll
                for (int it = 0; it < 16; ++it) {
                    int s = it >> 1, ntp = it & 1;
                    if (it < 15) {
                        int s2 = (it + 1) >> 1, ntp2 = (it + 1) & 1;
                        u32 kx2 = ((u32)s2 << 5) ^ kxor;
                        ldsm4(cw[(it + 1) & 1], rbd[ntp2] + (kx2 ^ sxd[ntp2]));
                    }
                    mma2(accdA + 8 * ntp, x2hA[s], cw[it & 1]);
                    mma2(accdB + 8 * ntp, x2hB[s], cw[it & 1]);
                }
            }
            float g0A = (grp == 0) ? cA0[0] : (grp == 1) ? c70[0] : cB0[0];
            float g1A = (grp == 0) ? cA1[0] : (grp == 1) ? c71[0] : cB1[0];
            float g0B = (grp == 0) ? cA0[1] : (grp == 1) ? c70[1] : cB0[1];
            float g1B = (grp == 0) ? cA1[1] : (grp == 1) ? c71[1] : cB1[1];
            #pragma unroll
            for (int ntp = 0; ntp < 2; ++ntp)
                #pragma unroll
                for (int tile = 0; tile < 2; ++tile) {
                    const float* A = accdA + 8 * ntp + 4 * tile;
                    const float* B = accdB + 8 * ntp + 4 * tile;
                    int vi = 4 * ntp + 2 * tile;
                    voutA[vi]     = fmaf(g0A, A[0], voutA[vi]);
                    voutA[vi + 1] = fmaf(g0A, A[1], voutA[vi + 1]);
                    voutA[vi + 8] = fmaf(g1A, A[2], voutA[vi + 8]);
                    voutA[vi + 9] = fmaf(g1A, A[3], voutA[vi + 9]);
                    voutB[vi]     = fmaf(g0B, B[0], voutB[vi]);
                    voutB[vi + 1] = fmaf(g0B, B[1], voutB[vi + 1]);
                    voutB[vi + 8] = fmaf(g1B, B[2], voutB[vi + 8]);
                    voutB[vi + 9] = fmaf(g1B, B[3], voutB[vi + 9]);
                }
        }

        // ---- stores ----
        #pragma unroll
        for (int ntp = 0; ntp < 2; ++ntp)
            #pragma unroll
            for (int tile = 0; tile < 2; ++tile) {
                int o = 16 * ntp + 8 * tile + kc;
                int vi = 4 * ntp + 2 * tile;
                *(float2*)(out + geA0 * 32 + o) = make_float2(voutA[vi], voutA[vi + 1]);
                *(float2*)(out + geA1 * 32 + o) = make_float2(voutA[vi + 8], voutA[vi + 9]);
                if (vB) {
                    *(float2*)(out + geB0 * 32 + o) = make_float2(voutB[vi], voutB[vi + 1]);
                    *(float2*)(out + geB1 * 32 + o) = make_float2(voutB[vi + 8], voutB[vi + 9]);
                }
            }

        ucur = unext;
    }
}

extern "C" void kernel_launch(void* const* d_in, const int* in_sizes, int n_in,
                              void* d_out, int out_size)
{
    const float* h_w  = (const float*)d_in[1];
    const float* e_vw = (const float*)d_in[2];
    const float* W0   = (const float*)d_in[3];
    const float* b0   = (const float*)d_in[4];
    const float* W1   = (const float*)d_in[5];
    const float* b1   = (const float*)d_in[6];
    const float* W2   = (const float*)d_in[7];
    const float* b2   = (const float*)d_in[8];
    float* out = (float*)d_out;

    prep<<<104, 256>>>(W0, W1, b0, b1, W2, b2);

    cudaFuncSetAttribute(msg_kernel, cudaFuncAttributeMaxDynamicSharedMemorySize, SMEM_BYTES);
    msg_kernel<<<GRID, NTHR, SMEM_BYTES>>>(h_w, e_vw, out);
}

// round 14
// speedup vs baseline: 1.0536x; 1.0536x over previous
#include <cuda_runtime.h>
#include <cuda_fp16.h>
#include <cstdint>

typedef unsigned int u32;

#define E_TOT   200000
#define GRID    148
#define NTHR    256
#define UNITS   6260            // 20 r-values x 313 node-blocks of 32

#define OFF_W0  0
#define OFF_W1  4096
#define OFF_T   36864
#define OFF_TB  102400
#define OFF_B0  103424
#define OFF_B1  103936
#define SMEM_BYTES 104448

__device__ uint4 gWimg[SMEM_BYTES / 16];
__device__ u32 gUC;             // work-stealing unit counter

// XOR-swizzled byte offset within a 256B-row fp16 image: row n, col k (0..127)
__host__ __device__ __forceinline__ u32 sw_off(int n, int k) {
    int chunk = k >> 3;
    return (u32)(n * 256 + (((chunk ^ (n & 7)) << 4) | ((k & 7) << 1)));
}

__device__ __forceinline__ void put16(u32 off, u32 boff, float v) {
    *(__half*)((char*)gWimg + off + boff) = __float2half(v);
}

// blocks 0..71: W0/W1 images + packed f16x2 bias pairs. blocks 72..103: T' + Tb.
__global__ void prep(const float* __restrict__ W0, const float* __restrict__ W1,
                     const float* __restrict__ b0, const float* __restrict__ b1,
                     const float* __restrict__ W2, const float* __restrict__ b2)
{
    int blk = blockIdx.x, tid = threadIdx.x;
    if (blk == 0 && tid == 0) gUC = 0;
    if (blk < 72) {
        int id = blk * 256 + tid;
        if (id < 2048) {                   // W0 [128n][16k], 32B rows, no swizzle
            int n = id >> 4, k = id & 15;
            put16(OFF_W0, (u32)(n * 32 + k * 2), W0[id]);
        } else if (id < 2048 + 16384) {    // W1 [128n][128k], swizzled
            int j = id - 2048;
            put16(OFF_W1, sw_off(j >> 7, j & 127), W1[j]);
        }
        if (id < 64) {                     // packed f16x2 bias pairs
            __half2 h = __floats2half2_rn(b0[2 * id], b0[2 * id + 1]);
            *(u32*)((char*)gWimg + OFF_B0 + id * 4) = *(u32*)&h;
        } else if (id < 128) {
            int p = id - 64;
            __half2 h = __floats2half2_rn(b1[2 * p], b1[2 * p + 1]);
            *(u32*)((char*)gWimg + OFF_B1 + p * 4) = *(u32*)&h;
        }
    } else {
        int o = blk - 72, j = tid & 127;
        if (tid < 128) {
            float s = 0.f;
            #pragma unroll
            for (int i = 0; i < 32; ++i) {
                s += W2[(o * 32 + i) * 128 + j];
                if ((i & 3) == 3) put16(OFF_T, sw_off((i >> 2) * 32 + o, j), s);
            }
        } else if (tid == 128) {
            float sb = 0.f;
            #pragma unroll
            for (int i = 0; i < 32; ++i) {
                sb += b2[o * 32 + i];
                if ((i & 3) == 3)
                    *(float*)((char*)gWimg + OFF_TB + ((i >> 2) * 32 + o) * 4) = sb;
            }
        }
    }
}

// ---------------------------------------------------------------------------
__device__ __forceinline__ u32 smem_u32(const void* p) {
    u32 a;
    asm("{ .reg .u64 t; cvta.to.shared.u64 t, %1; cvt.u32.u64 %0, t; }" : "=r"(a) : "l"(p));
    return a;
}
__device__ __forceinline__ void ldsm4(u32* r, u32 a) {
    asm volatile("ldmatrix.sync.aligned.m8n8.x4.shared.b16 {%0,%1,%2,%3}, [%4];"
        : "=r"(r[0]), "=r"(r[1]), "=r"(r[2]), "=r"(r[3]) : "r"(a));
}
// f32-accumulator mma (GEMM_D)
__device__ __forceinline__ void mma(float* d, const u32* a, const u32* b) {
    asm volatile("mma.sync.aligned.m16n8k16.row.col.f32.f16.f16.f32 "
        "{%0,%1,%2,%3}, {%4,%5,%6,%7}, {%8,%9}, {%0,%1,%2,%3};"
        : "+f"(d[0]), "+f"(d[1]), "+f"(d[2]), "+f"(d[3])
        : "r"(a[0]), "r"(a[1]), "r"(a[2]), "r"(a[3]), "r"(b[0]), "r"(b[1]));
}
__device__ __forceinline__ void mma2(float* acc, const u32* a, const u32* b) {
    mma(acc,     a, b);
    mma(acc + 4, a, b + 2);
}
// f16-accumulator mma: D fragments {d0,d1} ARE next-GEMM A fragments
__device__ __forceinline__ void mmah(u32* d, const u32* a, const u32* b) {
    asm volatile("mma.sync.aligned.m16n8k16.row.col.f16.f16.f16.f16 "
        "{%0,%1}, {%2,%3,%4,%5}, {%6,%7}, {%0,%1};"
        : "+r"(d[0]), "+r"(d[1])
        : "r"(a[0]), "r"(a[1]), "r"(a[2]), "r"(a[3]), "r"(b[0]), "r"(b[1]));
}
// two n8 tiles: d[0..1]=a0,a1 of k-lo block; d[2..3]=a2,a3 (k-hi block)
__device__ __forceinline__ void mma2h(u32* d, const u32* a, const u32* b) {
    mmah(d,     a, b);
    mmah(d + 2, a, b + 2);
}
__device__ __forceinline__ u32 hadd2_(u32 a, u32 b) {
    u32 r; asm("add.rn.f16x2 %0, %1, %2;" : "=r"(r) : "r"(a), "r"(b)); return r;
}
__device__ __forceinline__ u32 hrelu(u32 a) {
    u32 r; asm("max.f16x2 %0, %1, %2;" : "=r"(r) : "r"(a), "r"(0u)); return r;
}
__device__ __forceinline__ u32 pack2(float f0, float f1) {
    u32 h;
    asm("cvt.rn.f16x2.f32 %0, %1, %2;" : "=r"(h) : "f"(f1), "f"(f0));
    return h;
}

__global__ void __launch_bounds__(NTHR, 1)
msg_kernel(const float* __restrict__ h_w, const float* __restrict__ e_vw,
           float* __restrict__ out)
{
    extern __shared__ unsigned char sraw[];
    const int t = threadIdx.x, lane = t & 31;
    const int lr = lane & 7, g = lane >> 3, q = lane & 3;
    const int kc = 2 * q;
    const int el = lane >> 2;

    // stage weight image (102KB)
    {
        uint4* dst = (uint4*)sraw;
        for (int i = t; i < SMEM_BYTES / 16; i += NTHR) dst[i] = gWimg[i];
    }
    __syncthreads();

    const u32 sb = smem_u32(sraw);
    const u32*   b0ps = (const u32*)(sraw + OFF_B0);
    const u32*   b1ps = (const u32*)(sraw + OFF_B1);
    const float* Tbs  = (const float*)(sraw + OFF_TB);

    // per-slice address bases (unit-invariant)
    u32 rb1[8], sx1[8], ad0[8];
    #pragma unroll
    for (int s = 0; s < 8; ++s) {
        int n = (2 * s + (g >> 1)) * 8 + lr;
        rb1[s] = sb + OFF_W1 + n * 256;
        sx1[s] = (u32)(n & 7) << 4;
        ad0[s] = sb + OFF_W0 + n * 32 + (g & 1) * 16;
    }
    const u32 kxor = (u32)(g & 1) << 4;

    // ---- work stealing ----
    u32 ucur;
    if (lane == 0) ucur = atomicAdd(&gUC, 1u);
    ucur = __shfl_sync(0xffffffffu, ucur, 0);

    while (ucur < UNITS) {
        const int u = (int)ucur;
        u32 unext;
        if (lane == 0) unext = atomicAdd(&gUC, 1u);
        unext = __shfl_sync(0xffffffffu, unext, 0);

        const int r = u % 20, bblk = u / 20;
        const bool vB = bblk < 312;
        const int nA = bblk * 32 + el;
        const int nB = vB ? nA + 16 : nA;
        const size_t geA0 = (size_t)nA * 20 + r, geA1 = geA0 + 160;
        const size_t geB0 = (size_t)nB * 20 + r, geB1 = geB0 + 160;

        // ---- warp-uniform telescoping structure ----
        const int rm = (r * 32) % 20;
        const int i1 = rm ? 20 - rm : 20;
        const int v0 = (r * 32) / 20;
        const int mA = (i1 >> 2) - 1;
        const bool hasB = (i1 + 20) < 32;
        const int mB = hasB ? ((i1 + 20) >> 2) - 1 : 7;

        // ---- per-edge coefficients ----
        float cA0[2], cA1[2], cB0[2], cB1[2], c70[2], c71[2];
        #pragma unroll
        for (int tl = 0; tl < 2; ++tl) {
            int n0 = (tl ? nB : nA) * 32 + v0;
            float h0a = h_w[n0], h1a = h_w[n0 + 1];
            float h0b = h_w[n0 + 256], h1b = h_w[n0 + 257];
            cA0[tl] = h0a - h1a; cA1[tl] = h0b - h1b;
            if (hasB) {
                float h2a = h_w[n0 + 2], h2b = h_w[n0 + 258];
                cB0[tl] = h1a - h2a; cB1[tl] = h1b - h2b;
                c70[tl] = h2a; c71[tl] = h2b;
            } else {
                cB0[tl] = 0.f; cB1[tl] = 0.f;
                c70[tl] = h1a; c71[tl] = h1b;
            }
        }

        // ---- e fragments, both tiles ----
        u32 ahA[4], ahB[4];
        {
            float2 u0 = *(const float2*)(e_vw + geA0 * 16 + kc);
            float2 u1 = *(const float2*)(e_vw + geA0 * 16 + kc + 8);
            float2 u2 = *(const float2*)(e_vw + geA1 * 16 + kc);
            float2 u3 = *(const float2*)(e_vw + geA1 * 16 + kc + 8);
            ahA[0] = pack2(u0.x, u0.y);
            ahA[1] = pack2(u2.x, u2.y);
            ahA[2] = pack2(u1.x, u1.y);
            ahA[3] = pack2(u3.x, u3.y);
            u0 = *(const float2*)(e_vw + geB0 * 16 + kc);
            u1 = *(const float2*)(e_vw + geB0 * 16 + kc + 8);
            u2 = *(const float2*)(e_vw + geB1 * 16 + kc);
            u3 = *(const float2*)(e_vw + geB1 * 16 + kc + 8);
            ahB[0] = pack2(u0.x, u0.y);
            ahB[1] = pack2(u2.x, u2.y);
            ahB[2] = pack2(u1.x, u1.y);
            ahB[3] = pack2(u3.x, u3.y);
        }

        // ---- fused GEMM0->GEMM1, two N-halves; f16 dual-chain accumulators ----
        u32 x2hA[8][4], x2hB[8][4];
        #pragma unroll
        for (int half = 0; half < 2; ++half) {
            // chain E (bias-seeded, even chunks) and chain O (zero, odd chunks)
            u32 aeA[4][4], aoA[4][4], aeB[4][4], aoB[4][4];
            #pragma unroll
            for (int n2 = 0; n2 < 4; ++n2) {
                int s2 = 4 * half + n2;
                u32 bE0 = b1ps[8 * s2 + q], bE1 = b1ps[8 * s2 + 4 + q];
                aeA[n2][0] = bE0; aeA[n2][1] = bE0; aeA[n2][2] = bE1; aeA[n2][3] = bE1;
                aeB[n2][0] = bE0; aeB[n2][1] = bE0; aeB[n2][2] = bE1; aeB[n2][3] = bE1;
                aoA[n2][0] = 0; aoA[n2][1] = 0; aoA[n2][2] = 0; aoA[n2][3] = 0;
                aoB[n2][0] = 0; aoB[n2][1] = 0; aoB[n2][2] = 0; aoB[n2][3] = 0;
            }
            u32 cw[2][4];
            ldsm4(cw[0], ad0[0]);                     // W0 slice 0
            #pragma unroll
            for (int s = 0; s < 8; ++s) {
                const u32 kx = ((u32)s << 5) ^ kxor;
                const int b0i = (5 * s) & 1;          // buffer holding W0(s)
                ldsm4(cw[b0i ^ 1], rb1[4 * half] + (kx ^ sx1[4 * half]));
                // GEMM0 slice s: f16 acc seeded with packed b0, single mma
                u32 x1A[4], x1B[4];
                {
                    u32 bb0 = b0ps[8 * s + q], bb1 = b0ps[8 * s + 4 + q];
                    x1A[0] = bb0; x1A[1] = bb0; x1A[2] = bb1; x1A[3] = bb1;
                    x1B[0] = bb0; x1B[1] = bb0; x1B[2] = bb1; x1B[3] = bb1;
                }
                mma2h(x1A, ahA, cw[b0i]);
                mma2h(x1B, ahB, cw[b0i]);
                x1A[0] = hrelu(x1A[0]); x1A[1] = hrelu(x1A[1]);
                x1A[2] = hrelu(x1A[2]); x1A[3] = hrelu(x1A[3]);
                x1B[0] = hrelu(x1B[0]); x1B[1] = hrelu(x1B[1]);
                x1B[2] = hrelu(x1B[2]); x1B[3] = hrelu(x1B[3]);
                // GEMM1 partial: chunk s into chain E (even) or O (odd)
                #pragma unroll
                for (int n2 = 0; n2 < 4; ++n2) {
                    const int bi = (5 * s + 1 + n2) & 1;
                    if (n2 < 3)
                        ldsm4(cw[bi ^ 1], rb1[4 * half + n2 + 1] + (kx ^ sx1[4 * half + n2 + 1]));
                    else if (s < 7)
                        ldsm4(cw[bi ^ 1], ad0[s + 1]);
                    if (s & 1) {
                        mma2h(aoA[n2], x1A, cw[bi]);
                        mma2h(aoB[n2], x1B, cw[bi]);
                    } else {
                        mma2h(aeA[n2], x1A, cw[bi]);
                        mma2h(aeB[n2], x1B, cw[bi]);
                    }
                }
            }
            // combine chains + relu -> x2 fragments (in fragment layout already)
            #pragma unroll
            for (int n2 = 0; n2 < 4; ++n2) {
                int s2 = 4 * half + n2;
                #pragma unroll
                for (int i = 0; i < 4; ++i) {
                    x2hA[s2][i] = hrelu(hadd2_(aeA[n2][i], aoA[n2][i]));
                    x2hB[s2][i] = hrelu(hadd2_(aeB[n2][i], aoB[n2][i]));
                }
            }
        }

        // ---- GEMM_D (f32 acc) over only the needed m-groups ----
        int   mlist[3] = { mA, 7, mB };
        const int ng = hasB ? 3 : 2;

        float voutA[16], voutB[16];
        #pragma unroll
        for (int i = 0; i < 16; ++i) { voutA[i] = 0.f; voutB[i] = 0.f; }

        for (int grp = 0; grp < ng; ++grp) {
            const int m = mlist[grp];
            float accdA[16], accdB[16];
            #pragma unroll
            for (int ntp = 0; ntp < 2; ++ntp)        // init with Tb
                #pragma unroll
                for (int tile = 0; tile < 2; ++tile) {
                    int o = 16 * ntp + 8 * tile + kc;
                    float tb0 = Tbs[m * 32 + o], tb1 = Tbs[m * 32 + o + 1];
                    float* A = accdA + 8 * ntp + 4 * tile;
                    float* B = accdB + 8 * ntp + 4 * tile;
                    A[0]=tb0; A[1]=tb1; A[2]=tb0; A[3]=tb1;
                    B[0]=tb0; B[1]=tb1; B[2]=tb0; B[3]=tb1;
                }
            u32 rbd[2], sxd[2];
            #pragma unroll
            for (int ntp = 0; ntp < 2; ++ntp) {
                int n = m * 32 + (2 * ntp + (g >> 1)) * 8 + lr;
                rbd[ntp] = sb + OFF_T + n * 256;
                sxd[ntp] = (u32)(n & 7) << 4;
            }
            {
                u32 cw[2][4];
                ldsm4(cw[0], rbd[0] + (kxor ^ sxd[0]));
                #pragma unroll
                for (int it = 0; it < 16; ++it) {
                    int s = it >> 1, ntp = it & 1;
                    if (it < 15) {
                        int s2 = (it + 1) >> 1, ntp2 = (it + 1) & 1;
                        u32 kx2 = ((u32)s2 << 5) ^ kxor;
                        ldsm4(cw[(it + 1) & 1], rbd[ntp2] + (kx2 ^ sxd[ntp2]));
                    }
                    mma2(accdA + 8 * ntp, x2hA[s], cw[it & 1]);
                    mma2(accdB + 8 * ntp, x2hB[s], cw[it & 1]);
                }
            }
            float g0A = (grp == 0) ? cA0[0] : (grp == 1) ? c70[0] : cB0[0];
            float g1A = (grp == 0) ? cA1[0] : (grp == 1) ? c71[0] : cB1[0];
            float g0B = (grp == 0) ? cA0[1] : (grp == 1) ? c70[1] : cB0[1];
            float g1B = (grp == 0) ? cA1[1] : (grp == 1) ? c71[1] : cB1[1];
            #pragma unroll
            for (int ntp = 0; ntp < 2; ++ntp)
                #pragma unroll
                for (int tile = 0; tile < 2; ++tile) {
                    const float* A = accdA + 8 * ntp + 4 * tile;
                    const float* B = accdB + 8 * ntp + 4 * tile;
                    int vi = 4 * ntp + 2 * tile;
                    voutA[vi]     = fmaf(g0A, A[0], voutA[vi]);
                    voutA[vi + 1] = fmaf(g0A, A[1], voutA[vi + 1]);
                    voutA[vi + 8] = fmaf(g1A, A[2], voutA[vi + 8]);
                    voutA[vi + 9] = fmaf(g1A, A[3], voutA[vi + 9]);
                    voutB[vi]     = fmaf(g0B, B[0], voutB[vi]);
                    voutB[vi + 1] = fmaf(g0B, B[1], voutB[vi + 1]);
                    voutB[vi + 8] = fmaf(g1B, B[2], voutB[vi + 8]);
                    voutB[vi + 9] = fmaf(g1B, B[3], voutB[vi + 9]);
                }
        }

        // ---- stores ----
        #pragma unroll
        for (int ntp = 0; ntp < 2; ++ntp)
            #pragma unroll
            for (int tile = 0; tile < 2; ++tile) {
                int o = 16 * ntp + 8 * tile + kc;
                int vi = 4 * ntp + 2 * tile;
                *(float2*)(out + geA0 * 32 + o) = make_float2(voutA[vi], voutA[vi + 1]);
                *(float2*)(out + geA1 * 32 + o) = make_float2(voutA[vi + 8], voutA[vi + 9]);
                if (vB) {
                    *(float2*)(out + geB0 * 32 + o) = make_float2(voutB[vi], voutB[vi + 1]);
                    *(float2*)(out + geB1 * 32 + o) = make_float2(voutB[vi + 8], voutB[vi + 9]);
                }
            }

        ucur = unext;
    }
}

extern "C" void kernel_launch(void* const* d_in, const int* in_sizes, int n_in,
                              void* d_out, int out_size)
{
    const float* h_w  = (const float*)d_in[1];
    const float* e_vw = (const float*)d_in[2];
    const float* W0   = (const float*)d_in[3];
    const float* b0   = (const float*)d_in[4];
    const float* W1   = (const float*)d_in[5];
    const float* b1   = (const float*)d_in[6];
    const float* W2   = (const float*)d_in[7];
    const float* b2   = (const float*)d_in[8];
    float* out = (float*)d_out;

    prep<<<104, 256>>>(W0, W1, b0, b1, W2, b2);

    cudaFuncSetAttribute(msg_kernel, cudaFuncAttributeMaxDynamicSharedMemorySize, SMEM_BYTES);
    msg_kernel<<<GRID, NTHR, SMEM_BYTES>>>(h_w, e_vw, out);
}